// round 9
// baseline (speedup 1.0000x reference)
#include <cuda_runtime.h>

// Problem constants
#define N_OP   50000
#define N_DEV  5000
#define D      128
#define DE     16
#define FIN    144        // D + DE
#define OUTF   128
#define OUT_STRIDE 256    // D + OUTF

#define NE_TOTAL 2480000
#define NSEG     160000

// Segment bases (stacked order: prev, succ, serve, link, place)
#define SEG_PREV   0
#define SEG_SUCC   50000
#define SEG_SERVE  100000
#define SEG_LINK   150000
#define SEG_PLACE  155000

#define GRID_OP  391      // ceil(50000/128)
#define GRID_DEV 40       // ceil(5000/128)

__device__ int g_cnt[NSEG];
__device__ int g_off[NSEG];
__device__ int g_cur[NSEG];
__device__ int g_tilesum[256];
__device__ int g_slots[NE_TOTAL];

// ---------------------------------------------------------------------------
// f32x2 packed math helpers (sm_100a)
// ---------------------------------------------------------------------------
__device__ __forceinline__ void ffma2(unsigned long long& acc,
                                      unsigned long long a,
                                      unsigned long long b) {
    asm("fma.rn.f32x2 %0, %1, %2, %0;" : "+l"(acc) : "l"(a), "l"(b));
}
__device__ __forceinline__ unsigned long long pack_dup(float x) {
    unsigned long long r;
    asm("mov.b64 %0, {%1, %1};" : "=l"(r) : "f"(x));
    return r;
}
__device__ __forceinline__ float2 unpack2(unsigned long long v) {
    float2 f;
    asm("mov.b64 {%0, %1}, %2;" : "=f"(f.x), "=f"(f.y) : "l"(v));
    return f;
}

// ---------------------------------------------------------------------------
// 0) zero counters
// ---------------------------------------------------------------------------
__global__ void zero_cnt_kernel(int* __restrict__ p, int n) {
    int i = blockIdx.x * blockDim.x + threadIdx.x;
    if (i < n) p[i] = 0;
}

// ---------------------------------------------------------------------------
// 1) histogram over all edges (stacked)
// ---------------------------------------------------------------------------
__global__ void hist_kernel(const int* __restrict__ d0, int n0,
                            const int* __restrict__ d1, int n1,
                            const int* __restrict__ d2, int n2,
                            const int* __restrict__ d3, int n3,
                            const int* __restrict__ d4, int n4) {
    int i = blockIdx.x * blockDim.x + threadIdx.x;
    if (i < n0) { atomicAdd(&g_cnt[SEG_PREV  + d0[i]], 1); return; } i -= n0;
    if (i < n1) { atomicAdd(&g_cnt[SEG_SUCC  + d1[i]], 1); return; } i -= n1;
    if (i < n2) { atomicAdd(&g_cnt[SEG_SERVE + d2[i]], 1); return; } i -= n2;
    if (i < n3) { atomicAdd(&g_cnt[SEG_LINK  + d3[i]], 1); return; } i -= n3;
    if (i < n4) { atomicAdd(&g_cnt[SEG_PLACE + d4[i]], 1); }
}

// ---------------------------------------------------------------------------
// 2) per-tile exclusive scan (1024/tile) + tile totals
// ---------------------------------------------------------------------------
__global__ __launch_bounds__(1024)
void scan_tiles_kernel(const int* __restrict__ cnt, int* __restrict__ off,
                       int* __restrict__ tilesum, int n) {
    __shared__ int warp_sums[32];
    int tid  = threadIdx.x;
    int gid  = blockIdx.x * 1024 + tid;
    int lane = tid & 31, wid = tid >> 5;
    int v = (gid < n) ? cnt[gid] : 0;

    int x = v;
    #pragma unroll
    for (int d = 1; d < 32; d <<= 1) {
        int y = __shfl_up_sync(0xffffffffu, x, d);
        if (lane >= d) x += y;
    }
    if (lane == 31) warp_sums[wid] = x;
    __syncthreads();
    if (wid == 0) {
        int s = warp_sums[lane];
        #pragma unroll
        for (int d = 1; d < 32; d <<= 1) {
            int y = __shfl_up_sync(0xffffffffu, s, d);
            if (lane >= d) s += y;
        }
        warp_sums[lane] = s;
    }
    __syncthreads();
    int warp_off = (wid > 0) ? warp_sums[wid - 1] : 0;
    int incl = x + warp_off;
    if (gid < n) off[gid] = incl - v;
    if (tid == 1023) tilesum[blockIdx.x] = incl;
}

// ---------------------------------------------------------------------------
// 3) fixup: add prefix of tile sums, init cursors (one block per tile)
// ---------------------------------------------------------------------------
__global__ __launch_bounds__(1024)
void scan_fixup_kernel(int* __restrict__ off, const int* __restrict__ tilesum,
                       int* __restrict__ cur, int n) {
    __shared__ int red[32];
    __shared__ int s_prefix;
    int t    = blockIdx.x;
    int tid  = threadIdx.x;
    int lane = tid & 31, wid = tid >> 5;

    int partial = 0;
    for (int i = tid; i < t; i += 1024) partial += tilesum[i];
    #pragma unroll
    for (int d = 16; d > 0; d >>= 1)
        partial += __shfl_down_sync(0xffffffffu, partial, d);
    if (lane == 0) red[wid] = partial;
    __syncthreads();
    if (tid < 32) {
        int v = red[tid];
        #pragma unroll
        for (int d = 16; d > 0; d >>= 1)
            v += __shfl_down_sync(0xffffffffu, v, d);
        if (tid == 0) s_prefix = v;
    }
    __syncthreads();
    int prefix = s_prefix;

    int gid = t * 1024 + tid;
    if (gid < n) {
        int o = off[gid] + prefix;
        off[gid] = o;
        cur[gid] = o;
    }
}

// ---------------------------------------------------------------------------
// 4) bin edge IDs into dst buckets
// ---------------------------------------------------------------------------
__global__ void bin_kernel(const int* __restrict__ d0, int n0,
                           const int* __restrict__ d1, int n1,
                           const int* __restrict__ d2, int n2,
                           const int* __restrict__ d3, int n3,
                           const int* __restrict__ d4, int n4) {
    int e = blockIdx.x * blockDim.x + threadIdx.x;
    if (e < n0) { int s = atomicAdd(&g_cur[SEG_PREV  + d0[e]], 1); g_slots[s] = e; return; } e -= n0;
    if (e < n1) { int s = atomicAdd(&g_cur[SEG_SUCC  + d1[e]], 1); g_slots[s] = e; return; } e -= n1;
    if (e < n2) { int s = atomicAdd(&g_cur[SEG_SERVE + d2[e]], 1); g_slots[s] = e; return; } e -= n2;
    if (e < n3) { int s = atomicAdd(&g_cur[SEG_LINK  + d3[e]], 1); g_slots[s] = e; return; } e -= n3;
    if (e < n4) { int s = atomicAdd(&g_cur[SEG_PLACE + d4[e]], 1); g_slots[s] = e; }
}

// ---------------------------------------------------------------------------
// Row gather (R8-proven inner loop): warp accumulates one segment's 144-dim
// sum and writes it into the smem A tile (scalar STS; odd stride 145).
// ---------------------------------------------------------------------------
#define AS_STRIDE 145
#define AS_FLOATS (128 * AS_STRIDE)
#define WS_FLOATS (144 * 128)
#define FUSED_SMEM_BYTES ((AS_FLOATS + WS_FLOATS) * 4)

__device__ __forceinline__ void gather_row_to_smem(
        const float* __restrict__ sf, const float* __restrict__ ef,
        const int* __restrict__ src, int m, int base, int lane,
        float* __restrict__ As_row) {
    float4 f  = make_float4(0.f, 0.f, 0.f, 0.f);
    float4 e4 = make_float4(0.f, 0.f, 0.f, 0.f);

    for (int c = 0; c < m; c += 32) {
        int k = c + lane;
        int eidx = 0, sidx = 0;
        if (k < m) {
            eidx = __ldg(&g_slots[base + k]);
            sidx = __ldg(&src[eidx]);
        }
        int iter = min(32, m - c);

        int i = 0;
        for (; i + 4 <= iter; i += 4) {
            int s0 = __shfl_sync(0xffffffffu, sidx, i + 0);
            int s1 = __shfl_sync(0xffffffffu, sidx, i + 1);
            int s2 = __shfl_sync(0xffffffffu, sidx, i + 2);
            int s3 = __shfl_sync(0xffffffffu, sidx, i + 3);
            int emy = __shfl_sync(0xffffffffu, eidx, i + (lane >> 2));
            float4 v0 = __ldg(reinterpret_cast<const float4*>(sf + (size_t)s0 * D) + lane);
            float4 v1 = __ldg(reinterpret_cast<const float4*>(sf + (size_t)s1 * D) + lane);
            float4 v2 = __ldg(reinterpret_cast<const float4*>(sf + (size_t)s2 * D) + lane);
            float4 v3 = __ldg(reinterpret_cast<const float4*>(sf + (size_t)s3 * D) + lane);
            if (lane < 16) {
                float4 t = __ldg(reinterpret_cast<const float4*>(ef + (size_t)emy * DE) + (lane & 3));
                e4.x += t.x; e4.y += t.y; e4.z += t.z; e4.w += t.w;
            }
            f.x += v0.x; f.y += v0.y; f.z += v0.z; f.w += v0.w;
            f.x += v1.x; f.y += v1.y; f.z += v1.z; f.w += v1.w;
            f.x += v2.x; f.y += v2.y; f.z += v2.z; f.w += v2.w;
            f.x += v3.x; f.y += v3.y; f.z += v3.z; f.w += v3.w;
        }
        for (; i < iter; i++) {
            int s = __shfl_sync(0xffffffffu, sidx, i);
            int e = __shfl_sync(0xffffffffu, eidx, i);
            float4 v = __ldg(reinterpret_cast<const float4*>(sf + (size_t)s * D) + lane);
            f.x += v.x; f.y += v.y; f.z += v.z; f.w += v.w;
            if (lane < 4) {
                float4 t = __ldg(reinterpret_cast<const float4*>(ef + (size_t)e * DE) + lane);
                e4.x += t.x; e4.y += t.y; e4.z += t.z; e4.w += t.w;
            }
        }
    }

    e4.x += __shfl_xor_sync(0xffffffffu, e4.x, 4);
    e4.y += __shfl_xor_sync(0xffffffffu, e4.y, 4);
    e4.z += __shfl_xor_sync(0xffffffffu, e4.z, 4);
    e4.w += __shfl_xor_sync(0xffffffffu, e4.w, 4);
    e4.x += __shfl_xor_sync(0xffffffffu, e4.x, 8);
    e4.y += __shfl_xor_sync(0xffffffffu, e4.y, 8);
    e4.z += __shfl_xor_sync(0xffffffffu, e4.z, 8);
    e4.w += __shfl_xor_sync(0xffffffffu, e4.w, 8);

    // scalar stores (stride 145 floats is not 16B aligned per row)
    float* p = As_row + lane * 4;
    p[0] = f.x; p[1] = f.y; p[2] = f.z; p[3] = f.w;
    if (lane < 4) {
        float* q = As_row + D + lane * 4;
        q[0] = e4.x; q[1] = e4.y; q[2] = e4.z; q[3] = e4.w;
    }
}

// ---------------------------------------------------------------------------
// 5) FUSED gather + GEMM. One block = 128 dst rows. Per etype:
//    sync -> load W to smem -> warps gather rows directly into As -> sync ->
//    f32x2 GEMM + gated epilogue. No global acc buffer.
// ---------------------------------------------------------------------------
__global__ __launch_bounds__(512)
void gconv_fused_kernel(const float* __restrict__ op_feats,
                        const float* __restrict__ dev_feats,
                        const float* __restrict__ ef_prev,  const int* __restrict__ src_prev,
                        const float* __restrict__ ef_succ,  const int* __restrict__ src_succ,
                        const float* __restrict__ ef_serve, const int* __restrict__ src_serve,
                        const float* __restrict__ ef_link,  const int* __restrict__ src_link,
                        const float* __restrict__ ef_place, const int* __restrict__ src_place,
                        const float* __restrict__ W_prev,  const float* __restrict__ b_prev,
                        const float* __restrict__ W_succ,  const float* __restrict__ b_succ,
                        const float* __restrict__ W_serve, const float* __restrict__ b_serve,
                        const float* __restrict__ W_link,  const float* __restrict__ b_link,
                        const float* __restrict__ W_place, const float* __restrict__ b_place,
                        float* __restrict__ out) {
    extern __shared__ float sm[];
    float* As = sm;                 // [128][145]
    float* Ws = sm + AS_FLOATS;     // [144][128]

    const int tid  = threadIdx.x;
    const int lane = tid & 31;
    const int wrp  = tid >> 5;      // 0..15
    const int c0   = wrp * 8;

    const bool is_op = blockIdx.x < GRID_OP;
    const int  net   = is_op ? 3 : 2;
    const int  row0  = (is_op ? blockIdx.x : (blockIdx.x - GRID_OP)) * 128;
    const int  n     = is_op ? N_OP : N_DEV;

    const float* feats = is_op ? op_feats : dev_feats;
    const float* sfA[3]; const float* efA[3]; const int* srcA[3];
    int segA[3]; const float* WA[3]; const float* bA[3];
    if (is_op) {
        sfA[0] = op_feats;  efA[0] = ef_prev;  srcA[0] = src_prev;  segA[0] = SEG_PREV;  WA[0] = W_prev;  bA[0] = b_prev;
        sfA[1] = op_feats;  efA[1] = ef_succ;  srcA[1] = src_succ;  segA[1] = SEG_SUCC;  WA[1] = W_succ;  bA[1] = b_succ;
        sfA[2] = dev_feats; efA[2] = ef_serve; srcA[2] = src_serve; segA[2] = SEG_SERVE; WA[2] = W_serve; bA[2] = b_serve;
    } else {
        sfA[0] = dev_feats; efA[0] = ef_link;  srcA[0] = src_link;  segA[0] = SEG_LINK;  WA[0] = W_link;  bA[0] = b_link;
        sfA[1] = op_feats;  efA[1] = ef_place; srcA[1] = src_place; segA[1] = SEG_PLACE; WA[1] = W_place; bA[1] = b_place;
        sfA[2] = sfA[1]; efA[2] = efA[1]; srcA[2] = srcA[1]; segA[2] = segA[1]; WA[2] = WA[1]; bA[2] = bA[1];
    }
    float* outp = is_op ? out : (out + (size_t)N_OP * OUT_STRIDE);

    float outv[4][8];
    #pragma unroll
    for (int q = 0; q < 4; q++)
        #pragma unroll
        for (int j = 0; j < 8; j++) outv[q][j] = 0.f;

    for (int et = 0; et < net; et++) {
        const float* W = WA[et];
        const float* sf = sfA[et];
        const float* ef = efA[et];
        const int* src = srcA[et];
        const int seg0 = segA[et];

        __syncthreads();   // previous GEMM done reading As/Ws

        // load W (4608 float4, 9 per thread)
        {
            const float4* W4 = reinterpret_cast<const float4*>(W);
            float4* Ws4 = reinterpret_cast<float4*>(Ws);
            #pragma unroll
            for (int i = 0; i < 9; i++) Ws4[tid + i * 512] = W4[tid + i * 512];
        }

        // gather: warp wrp handles local rows wrp + 16*j
        #pragma unroll 1
        for (int j = 0; j < 8; j++) {
            int lrow = wrp + 16 * j;
            int grow = row0 + lrow;
            if (grow < n) {
                int m = __ldg(&g_cnt[seg0 + grow]);
                if (m > 0) {
                    int base = __ldg(&g_off[seg0 + grow]);
                    gather_row_to_smem(sf, ef, src, m, base, lane,
                                       As + lrow * AS_STRIDE);
                }
            }
        }
        __syncthreads();   // As + Ws ready

        unsigned long long p2[4][4];
        #pragma unroll
        for (int q = 0; q < 4; q++)
            #pragma unroll
            for (int jj = 0; jj < 4; jj++) p2[q][jj] = 0ull;

        #pragma unroll 4
        for (int k = 0; k < FIN; k++) {
            const unsigned long long* Wrow =
                reinterpret_cast<const unsigned long long*>(Ws + k * 128 + c0);
            unsigned long long w0 = Wrow[0], w1 = Wrow[1], w2 = Wrow[2], w3 = Wrow[3];
            #pragma unroll
            for (int q = 0; q < 4; q++) {
                unsigned long long a2 = pack_dup(As[(lane + 32 * q) * AS_STRIDE + k]);
                ffma2(p2[q][0], a2, w0);
                ffma2(p2[q][1], a2, w1);
                ffma2(p2[q][2], a2, w2);
                ffma2(p2[q][3], a2, w3);
            }
        }

        const float* b = bA[et];
        #pragma unroll
        for (int q = 0; q < 4; q++) {
            int row = row0 + lane + q * 32;
            if (row < n) {
                int c = __ldg(&g_cnt[seg0 + row]);
                if (c > 0) {
                    float inv = 1.0f / (float)c;
                    #pragma unroll
                    for (int jj = 0; jj < 4; jj++) {
                        float2 pv = unpack2(p2[q][jj]);
                        outv[q][2 * jj]     += pv.x * inv + b[c0 + 2 * jj];
                        outv[q][2 * jj + 1] += pv.y * inv + b[c0 + 2 * jj + 1];
                    }
                }
            }
        }
    }

    const float invn = is_op ? (1.0f / 3.0f) : 0.5f;
    #pragma unroll
    for (int q = 0; q < 4; q++) {
        int row = row0 + lane + q * 32;
        if (row < n) {
            float*       orow = outp  + (size_t)row * OUT_STRIDE;
            const float* frow = feats + (size_t)row * D;
            #pragma unroll
            for (int jj = 0; jj < 8; jj++) {
                orow[c0 + jj]     = frow[c0 + jj];
                orow[D + c0 + jj] = fmaxf(outv[q][jj] * invn, 0.f);
            }
        }
    }
}

// ---------------------------------------------------------------------------
// Launch
// ---------------------------------------------------------------------------
extern "C" void kernel_launch(void* const* d_in, const int* in_sizes, int n_in,
                              void* d_out, int out_size) {
    const float* op_feats  = (const float*)d_in[0];
    const float* dev_feats = (const float*)d_in[1];

    const float* ef_link  = (const float*)d_in[2];
    const int*   src_link = (const int*)  d_in[3];
    const int*   dst_link = (const int*)  d_in[4];
    const float* W_link   = (const float*)d_in[5];
    const float* b_link   = (const float*)d_in[6];

    const float* ef_prev  = (const float*)d_in[7];
    const int*   src_prev = (const int*)  d_in[8];
    const int*   dst_prev = (const int*)  d_in[9];
    const float* W_prev   = (const float*)d_in[10];
    const float* b_prev   = (const float*)d_in[11];

    const float* ef_succ  = (const float*)d_in[12];
    const int*   src_succ = (const int*)  d_in[13];
    const int*   dst_succ = (const int*)  d_in[14];
    const float* W_succ   = (const float*)d_in[15];
    const float* b_succ   = (const float*)d_in[16];

    const float* ef_place  = (const float*)d_in[17];
    const int*   src_place = (const int*)  d_in[18];
    const int*   dst_place = (const int*)  d_in[19];
    const float* W_place   = (const float*)d_in[20];
    const float* b_place   = (const float*)d_in[21];

    const float* ef_serve  = (const float*)d_in[22];
    const int*   src_serve = (const int*)  d_in[23];
    const int*   dst_serve = (const int*)  d_in[24];
    const float* W_serve   = (const float*)d_in[25];
    const float* b_serve   = (const float*)d_in[26];

    const int ne_link  = in_sizes[3];
    const int ne_prev  = in_sizes[8];
    const int ne_succ  = in_sizes[13];
    const int ne_place = in_sizes[18];
    const int ne_serve = in_sizes[23];
    const int ne_total = ne_link + ne_prev + ne_succ + ne_place + ne_serve;

    int* cntbase = nullptr;  cudaGetSymbolAddress((void**)&cntbase, g_cnt);
    int* offbase = nullptr;  cudaGetSymbolAddress((void**)&offbase, g_off);
    int* curbase = nullptr;  cudaGetSymbolAddress((void**)&curbase, g_cur);
    int* tilesum = nullptr;  cudaGetSymbolAddress((void**)&tilesum, g_tilesum);

    cudaFuncSetAttribute(gconv_fused_kernel,
                         cudaFuncAttributeMaxDynamicSharedMemorySize,
                         FUSED_SMEM_BYTES);

    // 0) zero counters
    zero_cnt_kernel<<<(NSEG + 255) / 256, 256>>>(cntbase, NSEG);

    // 1) histogram
    hist_kernel<<<(ne_total + 255) / 256, 256>>>(
        dst_prev, ne_prev, dst_succ, ne_succ, dst_serve, ne_serve,
        dst_link, ne_link, dst_place, ne_place);

    // 2-3) scan
    int ntiles = (NSEG + 1023) / 1024;  // 157
    scan_tiles_kernel<<<ntiles, 1024>>>(cntbase, offbase, tilesum, NSEG);
    scan_fixup_kernel<<<ntiles, 1024>>>(offbase, tilesum, curbase, NSEG);

    // 4) bin
    bin_kernel<<<(ne_total + 255) / 256, 256>>>(
        dst_prev, ne_prev, dst_succ, ne_succ, dst_serve, ne_serve,
        dst_link, ne_link, dst_place, ne_place);

    // 5) fused gather + GEMM
    gconv_fused_kernel<<<GRID_OP + GRID_DEV, 512, FUSED_SMEM_BYTES>>>(
        op_feats, dev_feats,
        ef_prev, src_prev, ef_succ, src_succ, ef_serve, src_serve,
        ef_link, src_link, ef_place, src_place,
        W_prev, b_prev, W_succ, b_succ, W_serve, b_serve,
        W_link, b_link, W_place, b_place,
        (float*)d_out);

    (void)n_in; (void)out_size;
}

// round 11
// speedup vs baseline: 1.3159x; 1.3159x over previous
#include <cuda_runtime.h>

// Problem constants
#define N_OP   50000
#define N_DEV  5000
#define D      128
#define DE     16
#define FIN    144        // D + DE
#define OUTF   128
#define OUT_STRIDE 256    // D + OUTF

#define NE_TOTAL 2480000
#define NSEG     160000

// Segment bases (stacked order: prev, succ, serve, link, place)
#define SEG_PREV   0
#define SEG_SUCC   50000
#define SEG_SERVE  100000
#define SEG_LINK   150000
#define SEG_PLACE  155000

#define OFF_ACC_PREV   0
#define OFF_ACC_SUCC   7200000
#define OFF_ACC_SERVE  14400000
#define OFF_ACC_LINK   21600000
#define OFF_ACC_PLACE  22320000
#define ACC_FLOATS     23040000

#define GRID_OP  391      // ceil(50000/128)
#define GRID_DEV 40       // ceil(5000/128)

__device__ float g_acc[ACC_FLOATS];
__device__ int   g_cnt[NSEG];
__device__ int   g_off[NSEG];
__device__ int   g_cur[NSEG];
__device__ int   g_tilesum[256];
__device__ int   g_slots[NE_TOTAL];

// ---------------------------------------------------------------------------
// f32x2 packed math helpers (sm_100a)
// ---------------------------------------------------------------------------
__device__ __forceinline__ void ffma2(unsigned long long& acc,
                                      unsigned long long a,
                                      unsigned long long b) {
    asm("fma.rn.f32x2 %0, %1, %2, %0;" : "+l"(acc) : "l"(a), "l"(b));
}
__device__ __forceinline__ unsigned long long pack_dup(float x) {
    unsigned long long r;
    asm("mov.b64 %0, {%1, %1};" : "=l"(r) : "f"(x));
    return r;
}
__device__ __forceinline__ float2 unpack2(unsigned long long v) {
    float2 f;
    asm("mov.b64 {%0, %1}, %2;" : "=f"(f.x), "=f"(f.y) : "l"(v));
    return f;
}

// ---------------------------------------------------------------------------
// 0) zero counters
// ---------------------------------------------------------------------------
__global__ void zero_cnt_kernel(int* __restrict__ p, int n) {
    int i = blockIdx.x * blockDim.x + threadIdx.x;
    if (i < n) p[i] = 0;
}

// ---------------------------------------------------------------------------
// 1) histogram over all edges (stacked)
// ---------------------------------------------------------------------------
__global__ void hist_kernel(const int* __restrict__ d0, int n0,
                            const int* __restrict__ d1, int n1,
                            const int* __restrict__ d2, int n2,
                            const int* __restrict__ d3, int n3,
                            const int* __restrict__ d4, int n4) {
    int i = blockIdx.x * blockDim.x + threadIdx.x;
    if (i < n0) { atomicAdd(&g_cnt[SEG_PREV  + d0[i]], 1); return; } i -= n0;
    if (i < n1) { atomicAdd(&g_cnt[SEG_SUCC  + d1[i]], 1); return; } i -= n1;
    if (i < n2) { atomicAdd(&g_cnt[SEG_SERVE + d2[i]], 1); return; } i -= n2;
    if (i < n3) { atomicAdd(&g_cnt[SEG_LINK  + d3[i]], 1); return; } i -= n3;
    if (i < n4) { atomicAdd(&g_cnt[SEG_PLACE + d4[i]], 1); }
}

// ---------------------------------------------------------------------------
// 2) per-tile exclusive scan (1024/tile) + tile totals
// ---------------------------------------------------------------------------
__global__ __launch_bounds__(1024)
void scan_tiles_kernel(const int* __restrict__ cnt, int* __restrict__ off,
                       int* __restrict__ tilesum, int n) {
    __shared__ int warp_sums[32];
    int tid  = threadIdx.x;
    int gid  = blockIdx.x * 1024 + tid;
    int lane = tid & 31, wid = tid >> 5;
    int v = (gid < n) ? cnt[gid] : 0;

    int x = v;
    #pragma unroll
    for (int d = 1; d < 32; d <<= 1) {
        int y = __shfl_up_sync(0xffffffffu, x, d);
        if (lane >= d) x += y;
    }
    if (lane == 31) warp_sums[wid] = x;
    __syncthreads();
    if (wid == 0) {
        int s = warp_sums[lane];
        #pragma unroll
        for (int d = 1; d < 32; d <<= 1) {
            int y = __shfl_up_sync(0xffffffffu, s, d);
            if (lane >= d) s += y;
        }
        warp_sums[lane] = s;
    }
    __syncthreads();
    int warp_off = (wid > 0) ? warp_sums[wid - 1] : 0;
    int incl = x + warp_off;
    if (gid < n) off[gid] = incl - v;
    if (tid == 1023) tilesum[blockIdx.x] = incl;
}

// ---------------------------------------------------------------------------
// 3) fixup: add prefix of tile sums, init cursors (one block per tile)
// ---------------------------------------------------------------------------
__global__ __launch_bounds__(1024)
void scan_fixup_kernel(int* __restrict__ off, const int* __restrict__ tilesum,
                       int* __restrict__ cur, int n) {
    __shared__ int red[32];
    __shared__ int s_prefix;
    int t    = blockIdx.x;
    int tid  = threadIdx.x;
    int lane = tid & 31, wid = tid >> 5;

    int partial = 0;
    for (int i = tid; i < t; i += 1024) partial += tilesum[i];
    #pragma unroll
    for (int d = 16; d > 0; d >>= 1)
        partial += __shfl_down_sync(0xffffffffu, partial, d);
    if (lane == 0) red[wid] = partial;
    __syncthreads();
    if (tid < 32) {
        int v = red[tid];
        #pragma unroll
        for (int d = 16; d > 0; d >>= 1)
            v += __shfl_down_sync(0xffffffffu, v, d);
        if (tid == 0) s_prefix = v;
    }
    __syncthreads();
    int prefix = s_prefix;

    int gid = t * 1024 + tid;
    if (gid < n) {
        int o = off[gid] + prefix;
        off[gid] = o;
        cur[gid] = o;
    }
}

// ---------------------------------------------------------------------------
// 4) bin edge IDs into dst buckets
// ---------------------------------------------------------------------------
__global__ void bin_kernel(const int* __restrict__ d0, int n0,
                           const int* __restrict__ d1, int n1,
                           const int* __restrict__ d2, int n2,
                           const int* __restrict__ d3, int n3,
                           const int* __restrict__ d4, int n4) {
    int e = blockIdx.x * blockDim.x + threadIdx.x;
    if (e < n0) { int s = atomicAdd(&g_cur[SEG_PREV  + d0[e]], 1); g_slots[s] = e; return; } e -= n0;
    if (e < n1) { int s = atomicAdd(&g_cur[SEG_SUCC  + d1[e]], 1); g_slots[s] = e; return; } e -= n1;
    if (e < n2) { int s = atomicAdd(&g_cur[SEG_SERVE + d2[e]], 1); g_slots[s] = e; return; } e -= n2;
    if (e < n3) { int s = atomicAdd(&g_cur[SEG_LINK  + d3[e]], 1); g_slots[s] = e; return; } e -= n3;
    if (e < n4) { int s = atomicAdd(&g_cur[SEG_PLACE + d4[e]], 1); g_slots[s] = e; }
}

// ---------------------------------------------------------------------------
// 5) fused gather: one warp per (etype, dst) segment; edge loop batched by 8 —
// eight independent 512B row loads (8x LDG.128/lane) in flight before any
// accumulation. ef handled 4-edges-per-16-lanes per quad, reduced at end.
// ---------------------------------------------------------------------------
__global__ __launch_bounds__(256)
void gather_fused_kernel(const float* __restrict__ op_feats,
                         const float* __restrict__ dev_feats,
                         const float* __restrict__ ef_prev,  const int* __restrict__ src_prev,
                         const float* __restrict__ ef_succ,  const int* __restrict__ src_succ,
                         const float* __restrict__ ef_serve, const int* __restrict__ src_serve,
                         const float* __restrict__ ef_link,  const int* __restrict__ src_link,
                         const float* __restrict__ ef_place, const int* __restrict__ src_place) {
    int seg = blockIdx.x * 8 + (threadIdx.x >> 5);
    if (seg >= NSEG) return;
    const int lane = threadIdx.x & 31;

    const float* sf; const float* ef; const int* src; float* acc; int local;
    if (seg < SEG_SUCC)       { sf = op_feats;  ef = ef_prev;  src = src_prev;  acc = g_acc + OFF_ACC_PREV;  local = seg; }
    else if (seg < SEG_SERVE) { sf = op_feats;  ef = ef_succ;  src = src_succ;  acc = g_acc + OFF_ACC_SUCC;  local = seg - SEG_SUCC; }
    else if (seg < SEG_LINK)  { sf = dev_feats; ef = ef_serve; src = src_serve; acc = g_acc + OFF_ACC_SERVE; local = seg - SEG_SERVE; }
    else if (seg < SEG_PLACE) { sf = dev_feats; ef = ef_link;  src = src_link;  acc = g_acc + OFF_ACC_LINK;  local = seg - SEG_LINK; }
    else                      { sf = op_feats;  ef = ef_place; src = src_place; acc = g_acc + OFF_ACC_PLACE; local = seg - SEG_PLACE; }

    int m = g_cnt[seg];
    if (m == 0) return;
    int base = g_off[seg];

    float4 f  = make_float4(0.f, 0.f, 0.f, 0.f);
    float4 e4 = make_float4(0.f, 0.f, 0.f, 0.f);  // lanes 0..15: ef chunk (lane&3) partials

    for (int c = 0; c < m; c += 32) {
        int k = c + lane;
        int eidx = 0, sidx = 0;
        if (k < m) {
            eidx = __ldg(&g_slots[base + k]);
            sidx = __ldg(&src[eidx]);
        }
        int iter = min(32, m - c);

        int i = 0;
        // 8-edge batches: 8 independent full-row loads + 2 ef loads in flight
        for (; i + 8 <= iter; i += 8) {
            int s0 = __shfl_sync(0xffffffffu, sidx, i + 0);
            int s1 = __shfl_sync(0xffffffffu, sidx, i + 1);
            int s2 = __shfl_sync(0xffffffffu, sidx, i + 2);
            int s3 = __shfl_sync(0xffffffffu, sidx, i + 3);
            int s4 = __shfl_sync(0xffffffffu, sidx, i + 4);
            int s5 = __shfl_sync(0xffffffffu, sidx, i + 5);
            int s6 = __shfl_sync(0xffffffffu, sidx, i + 6);
            int s7 = __shfl_sync(0xffffffffu, sidx, i + 7);
            int emyA = __shfl_sync(0xffffffffu, eidx, i + (lane >> 2));       // quad 0
            int emyB = __shfl_sync(0xffffffffu, eidx, i + 4 + (lane >> 2));   // quad 1
            float4 v0 = __ldg(reinterpret_cast<const float4*>(sf + (size_t)s0 * D) + lane);
            float4 v1 = __ldg(reinterpret_cast<const float4*>(sf + (size_t)s1 * D) + lane);
            float4 v2 = __ldg(reinterpret_cast<const float4*>(sf + (size_t)s2 * D) + lane);
            float4 v3 = __ldg(reinterpret_cast<const float4*>(sf + (size_t)s3 * D) + lane);
            float4 v4 = __ldg(reinterpret_cast<const float4*>(sf + (size_t)s4 * D) + lane);
            float4 v5 = __ldg(reinterpret_cast<const float4*>(sf + (size_t)s5 * D) + lane);
            float4 v6 = __ldg(reinterpret_cast<const float4*>(sf + (size_t)s6 * D) + lane);
            float4 v7 = __ldg(reinterpret_cast<const float4*>(sf + (size_t)s7 * D) + lane);
            if (lane < 16) {
                float4 tA = __ldg(reinterpret_cast<const float4*>(ef + (size_t)emyA * DE) + (lane & 3));
                float4 tB = __ldg(reinterpret_cast<const float4*>(ef + (size_t)emyB * DE) + (lane & 3));
                e4.x += tA.x + tB.x; e4.y += tA.y + tB.y;
                e4.z += tA.z + tB.z; e4.w += tA.w + tB.w;
            }
            f.x += v0.x; f.y += v0.y; f.z += v0.z; f.w += v0.w;
            f.x += v1.x; f.y += v1.y; f.z += v1.z; f.w += v1.w;
            f.x += v2.x; f.y += v2.y; f.z += v2.z; f.w += v2.w;
            f.x += v3.x; f.y += v3.y; f.z += v3.z; f.w += v3.w;
            f.x += v4.x; f.y += v4.y; f.z += v4.z; f.w += v4.w;
            f.x += v5.x; f.y += v5.y; f.z += v5.z; f.w += v5.w;
            f.x += v6.x; f.y += v6.y; f.z += v6.z; f.w += v6.w;
            f.x += v7.x; f.y += v7.y; f.z += v7.z; f.w += v7.w;
        }
        // 4-edge batch
        for (; i + 4 <= iter; i += 4) {
            int s0 = __shfl_sync(0xffffffffu, sidx, i + 0);
            int s1 = __shfl_sync(0xffffffffu, sidx, i + 1);
            int s2 = __shfl_sync(0xffffffffu, sidx, i + 2);
            int s3 = __shfl_sync(0xffffffffu, sidx, i + 3);
            int emy = __shfl_sync(0xffffffffu, eidx, i + (lane >> 2));
            float4 v0 = __ldg(reinterpret_cast<const float4*>(sf + (size_t)s0 * D) + lane);
            float4 v1 = __ldg(reinterpret_cast<const float4*>(sf + (size_t)s1 * D) + lane);
            float4 v2 = __ldg(reinterpret_cast<const float4*>(sf + (size_t)s2 * D) + lane);
            float4 v3 = __ldg(reinterpret_cast<const float4*>(sf + (size_t)s3 * D) + lane);
            if (lane < 16) {
                float4 t = __ldg(reinterpret_cast<const float4*>(ef + (size_t)emy * DE) + (lane & 3));
                e4.x += t.x; e4.y += t.y; e4.z += t.z; e4.w += t.w;
            }
            f.x += v0.x; f.y += v0.y; f.z += v0.z; f.w += v0.w;
            f.x += v1.x; f.y += v1.y; f.z += v1.z; f.w += v1.w;
            f.x += v2.x; f.y += v2.y; f.z += v2.z; f.w += v2.w;
            f.x += v3.x; f.y += v3.y; f.z += v3.z; f.w += v3.w;
        }
        // tail (<= 3 edges)
        for (; i < iter; i++) {
            int s = __shfl_sync(0xffffffffu, sidx, i);
            int e = __shfl_sync(0xffffffffu, eidx, i);
            float4 v = __ldg(reinterpret_cast<const float4*>(sf + (size_t)s * D) + lane);
            f.x += v.x; f.y += v.y; f.z += v.z; f.w += v.w;
            if (lane < 4) {
                float4 t = __ldg(reinterpret_cast<const float4*>(ef + (size_t)e * DE) + lane);
                e4.x += t.x; e4.y += t.y; e4.z += t.z; e4.w += t.w;
            }
        }
    }

    // reduce e4 across the 4 ef-lane groups (lanes {c, c+4, c+8, c+12})
    e4.x += __shfl_xor_sync(0xffffffffu, e4.x, 4);
    e4.y += __shfl_xor_sync(0xffffffffu, e4.y, 4);
    e4.z += __shfl_xor_sync(0xffffffffu, e4.z, 4);
    e4.w += __shfl_xor_sync(0xffffffffu, e4.w, 4);
    e4.x += __shfl_xor_sync(0xffffffffu, e4.x, 8);
    e4.y += __shfl_xor_sync(0xffffffffu, e4.y, 8);
    e4.z += __shfl_xor_sync(0xffffffffu, e4.z, 8);
    e4.w += __shfl_xor_sync(0xffffffffu, e4.w, 8);

    float* arow = acc + (size_t)local * FIN;
    reinterpret_cast<float4*>(arow)[lane] = f;
    if (lane < 4) reinterpret_cast<float4*>(arow + D)[lane] = e4;
}

// ---------------------------------------------------------------------------
// 6) fused GEMM (op + dev tiles in one grid), whole-K smem residency, f32x2.
// ---------------------------------------------------------------------------
#define AS_STRIDE 145
#define AS_FLOATS (128 * AS_STRIDE)
#define WS_FLOATS (144 * 128)
#define GEMM_SMEM_BYTES ((AS_FLOATS + WS_FLOATS) * 4)

__global__ __launch_bounds__(512)
void gemm_fused_kernel(const float* __restrict__ op_feats,
                       const float* __restrict__ dev_feats,
                       const float* __restrict__ W_prev,  const float* __restrict__ b_prev,
                       const float* __restrict__ W_succ,  const float* __restrict__ b_succ,
                       const float* __restrict__ W_serve, const float* __restrict__ b_serve,
                       const float* __restrict__ W_link,  const float* __restrict__ b_link,
                       const float* __restrict__ W_place, const float* __restrict__ b_place,
                       float* __restrict__ out) {
    extern __shared__ float sm[];
    float* As = sm;                 // [128][145]
    float* Ws = sm + AS_FLOATS;     // [144][128]

    const int tid = threadIdx.x;
    const int r   = tid & 31;
    const int c0  = (tid >> 5) * 8;

    const bool is_op = blockIdx.x < GRID_OP;
    const int  net   = is_op ? 3 : 2;
    const int  row0  = (is_op ? blockIdx.x : (blockIdx.x - GRID_OP)) * 128;
    const int  n     = is_op ? N_OP : N_DEV;

    const float* feats = is_op ? op_feats : dev_feats;
    const float* accA[3]; const int* cntA[3]; const float* WA[3]; const float* bA[3];
    if (is_op) {
        accA[0] = g_acc + OFF_ACC_PREV;  cntA[0] = g_cnt + SEG_PREV;  WA[0] = W_prev;  bA[0] = b_prev;
        accA[1] = g_acc + OFF_ACC_SUCC;  cntA[1] = g_cnt + SEG_SUCC;  WA[1] = W_succ;  bA[1] = b_succ;
        accA[2] = g_acc + OFF_ACC_SERVE; cntA[2] = g_cnt + SEG_SERVE; WA[2] = W_serve; bA[2] = b_serve;
    } else {
        accA[0] = g_acc + OFF_ACC_LINK;  cntA[0] = g_cnt + SEG_LINK;  WA[0] = W_link;  bA[0] = b_link;
        accA[1] = g_acc + OFF_ACC_PLACE; cntA[1] = g_cnt + SEG_PLACE; WA[1] = W_place; bA[1] = b_place;
        accA[2] = accA[1]; cntA[2] = cntA[1]; WA[2] = WA[1]; bA[2] = bA[1];
    }
    float* outp = is_op ? out : (out + (size_t)N_OP * OUT_STRIDE);

    float outv[4][8];
    #pragma unroll
    for (int q = 0; q < 4; q++)
        #pragma unroll
        for (int j = 0; j < 8; j++) outv[q][j] = 0.f;

    for (int et = 0; et < net; et++) {
        const float* acc = accA[et];
        const float* W   = WA[et];

        __syncthreads();
        {
            const float4* W4 = reinterpret_cast<const float4*>(W);
            float4* Ws4 = reinterpret_cast<float4*>(Ws);
            #pragma unroll
            for (int i = 0; i < 9; i++) Ws4[tid + i * 512] = W4[tid + i * 512];
        }
        {
            #pragma unroll
            for (int i = 0; i < 9; i++) {
                int idx = tid + i * 512;
                int rr  = idx / 36;
                int cc  = idx - rr * 36;
                float4 v = make_float4(0.f, 0.f, 0.f, 0.f);
                if (row0 + rr < n)
                    v = reinterpret_cast<const float4*>(acc + (size_t)(row0 + rr) * FIN)[cc];
                float* dst = As + rr * AS_STRIDE + cc * 4;
                dst[0] = v.x; dst[1] = v.y; dst[2] = v.z; dst[3] = v.w;
            }
        }
        __syncthreads();

        unsigned long long p2[4][4];
        #pragma unroll
        for (int q = 0; q < 4; q++)
            #pragma unroll
            for (int j = 0; j < 4; j++) p2[q][j] = 0ull;

        #pragma unroll 4
        for (int k = 0; k < FIN; k++) {
            const unsigned long long* Wrow =
                reinterpret_cast<const unsigned long long*>(Ws + k * 128 + c0);
            unsigned long long w0 = Wrow[0], w1 = Wrow[1], w2 = Wrow[2], w3 = Wrow[3];
            #pragma unroll
            for (int q = 0; q < 4; q++) {
                unsigned long long a2 = pack_dup(As[(r + 32 * q) * AS_STRIDE + k]);
                ffma2(p2[q][0], a2, w0);
                ffma2(p2[q][1], a2, w1);
                ffma2(p2[q][2], a2, w2);
                ffma2(p2[q][3], a2, w3);
            }
        }

        const int*   cnt = cntA[et];
        const float* b   = bA[et];
        #pragma unroll
        for (int q = 0; q < 4; q++) {
            int row = row0 + r + q * 32;
            if (row < n) {
                int c = cnt[row];
                if (c > 0) {
                    float inv = 1.0f / (float)c;
                    #pragma unroll
                    for (int j = 0; j < 4; j++) {
                        float2 pv = unpack2(p2[q][j]);
                        outv[q][2 * j]     += pv.x * inv + b[c0 + 2 * j];
                        outv[q][2 * j + 1] += pv.y * inv + b[c0 + 2 * j + 1];
                    }
                }
            }
        }
    }

    const float invn = is_op ? (1.0f / 3.0f) : 0.5f;
    #pragma unroll
    for (int q = 0; q < 4; q++) {
        int row = row0 + r + q * 32;
        if (row < n) {
            float*       orow = outp  + (size_t)row * OUT_STRIDE;
            const float* frow = feats + (size_t)row * D;
            #pragma unroll
            for (int j = 0; j < 8; j++) {
                orow[c0 + j]     = frow[c0 + j];
                orow[D + c0 + j] = fmaxf(outv[q][j] * invn, 0.f);
            }
        }
    }
}

// ---------------------------------------------------------------------------
// Launch
// ---------------------------------------------------------------------------
extern "C" void kernel_launch(void* const* d_in, const int* in_sizes, int n_in,
                              void* d_out, int out_size) {
    const float* op_feats  = (const float*)d_in[0];
    const float* dev_feats = (const float*)d_in[1];

    const float* ef_link  = (const float*)d_in[2];
    const int*   src_link = (const int*)  d_in[3];
    const int*   dst_link = (const int*)  d_in[4];
    const float* W_link   = (const float*)d_in[5];
    const float* b_link   = (const float*)d_in[6];

    const float* ef_prev  = (const float*)d_in[7];
    const int*   src_prev = (const int*)  d_in[8];
    const int*   dst_prev = (const int*)  d_in[9];
    const float* W_prev   = (const float*)d_in[10];
    const float* b_prev   = (const float*)d_in[11];

    const float* ef_succ  = (const float*)d_in[12];
    const int*   src_succ = (const int*)  d_in[13];
    const int*   dst_succ = (const int*)  d_in[14];
    const float* W_succ   = (const float*)d_in[15];
    const float* b_succ   = (const float*)d_in[16];

    const float* ef_place  = (const float*)d_in[17];
    const int*   src_place = (const int*)  d_in[18];
    const int*   dst_place = (const int*)  d_in[19];
    const float* W_place   = (const float*)d_in[20];
    const float* b_place   = (const float*)d_in[21];

    const float* ef_serve  = (const float*)d_in[22];
    const int*   src_serve = (const int*)  d_in[23];
    const int*   dst_serve = (const int*)  d_in[24];
    const float* W_serve   = (const float*)d_in[25];
    const float* b_serve   = (const float*)d_in[26];

    const int ne_link  = in_sizes[3];
    const int ne_prev  = in_sizes[8];
    const int ne_succ  = in_sizes[13];
    const int ne_place = in_sizes[18];
    const int ne_serve = in_sizes[23];
    const int ne_total = ne_link + ne_prev + ne_succ + ne_place + ne_serve;

    int* cntbase = nullptr;  cudaGetSymbolAddress((void**)&cntbase, g_cnt);
    int* offbase = nullptr;  cudaGetSymbolAddress((void**)&offbase, g_off);
    int* curbase = nullptr;  cudaGetSymbolAddress((void**)&curbase, g_cur);
    int* tilesum = nullptr;  cudaGetSymbolAddress((void**)&tilesum, g_tilesum);

    cudaFuncSetAttribute(gemm_fused_kernel,
                         cudaFuncAttributeMaxDynamicSharedMemorySize,
                         GEMM_SMEM_BYTES);

    // 0) zero counters
    zero_cnt_kernel<<<(NSEG + 255) / 256, 256>>>(cntbase, NSEG);

    // 1) histogram
    hist_kernel<<<(ne_total + 255) / 256, 256>>>(
        dst_prev, ne_prev, dst_succ, ne_succ, dst_serve, ne_serve,
        dst_link, ne_link, dst_place, ne_place);

    // 2-3) scan
    int ntiles = (NSEG + 1023) / 1024;  // 157
    scan_tiles_kernel<<<ntiles, 1024>>>(cntbase, offbase, tilesum, NSEG);
    scan_fixup_kernel<<<ntiles, 1024>>>(offbase, tilesum, curbase, NSEG);

    // 4) bin
    bin_kernel<<<(ne_total + 255) / 256, 256>>>(
        dst_prev, ne_prev, dst_succ, ne_succ, dst_serve, ne_serve,
        dst_link, ne_link, dst_place, ne_place);

    // 5) fused gather (one warp per segment, 8-edge load batching)
    gather_fused_kernel<<<(NSEG + 7) / 8, 256>>>(
        op_feats, dev_feats,
        ef_prev, src_prev, ef_succ, src_succ, ef_serve, src_serve,
        ef_link, src_link, ef_place, src_place);

    // 6) fused GEMM
    gemm_fused_kernel<<<GRID_OP + GRID_DEV, 512, GEMM_SMEM_BYTES>>>(
        op_feats, dev_feats,
        W_prev, b_prev, W_succ, b_succ, W_serve, b_serve,
        W_link, b_link, W_place, b_place,
        (float*)d_out);

    (void)n_in; (void)out_size;
}

// round 13
// speedup vs baseline: 1.4152x; 1.0755x over previous
#include <cuda_runtime.h>
#include <cuda_fp16.h>

// Problem constants
#define N_OP   50000
#define N_DEV  5000
#define D      128
#define DE     16
#define FIN    144        // D + DE
#define OUTF   128
#define OUT_STRIDE 256    // D + OUTF

#define NE_TOTAL 2480000
#define NSEG     160000

// Segment bases (stacked order: prev, succ, serve, link, place)
#define SEG_PREV   0
#define SEG_SUCC   50000
#define SEG_SERVE  100000
#define SEG_LINK   150000
#define SEG_PLACE  155000

#define OFF_ACC_PREV   0
#define OFF_ACC_SUCC   7200000
#define OFF_ACC_SERVE  14400000
#define OFF_ACC_LINK   21600000
#define OFF_ACC_PLACE  22320000
#define ACC_FLOATS     23040000

// fp16 feats: op at 0 (6,400,000 halves), dev at 6,400,000 (640,000 halves)
#define F16_OP_BASE   0
#define F16_DEV_BASE  6400000
#define F16_TOTAL     7040000
#define CONV_QUADS    1760000   // F16_TOTAL / 4
#define OP_QUADS      1600000

#define GRID_OP  391      // ceil(50000/128)
#define GRID_DEV 40       // ceil(5000/128)

__device__ float  g_acc[ACC_FLOATS];
__device__ __half g_feats16[F16_TOTAL];
__device__ int    g_cnt[NSEG];
__device__ int    g_off[NSEG];
__device__ int    g_cur[NSEG];
__device__ int    g_tilesum[256];
__device__ int    g_slots[NE_TOTAL];

// ---------------------------------------------------------------------------
// f32x2 packed math helpers (sm_100a)
// ---------------------------------------------------------------------------
__device__ __forceinline__ void ffma2(unsigned long long& acc,
                                      unsigned long long a,
                                      unsigned long long b) {
    asm("fma.rn.f32x2 %0, %1, %2, %0;" : "+l"(acc) : "l"(a), "l"(b));
}
__device__ __forceinline__ unsigned long long pack_dup(float x) {
    unsigned long long r;
    asm("mov.b64 %0, {%1, %1};" : "=l"(r) : "f"(x));
    return r;
}
__device__ __forceinline__ float2 unpack2(unsigned long long v) {
    float2 f;
    asm("mov.b64 {%0, %1}, %2;" : "=f"(f.x), "=f"(f.y) : "l"(v));
    return f;
}

// accumulate 4 fp16 values (packed in uint2) into float4
__device__ __forceinline__ void acc_h4(float4& f, uint2 u) {
    __half2 h0 = *reinterpret_cast<__half2*>(&u.x);
    __half2 h1 = *reinterpret_cast<__half2*>(&u.y);
    float2 a = __half22float2(h0);
    float2 b = __half22float2(h1);
    f.x += a.x; f.y += a.y; f.z += b.x; f.w += b.y;
}

// ---------------------------------------------------------------------------
// 0) prep: zero counters + convert feats to fp16 (one launch)
// ---------------------------------------------------------------------------
__global__ void prep_kernel(const float* __restrict__ op_feats,
                            const float* __restrict__ dev_feats) {
    int i = blockIdx.x * blockDim.x + threadIdx.x;
    if (i < NSEG) g_cnt[i] = 0;
    if (i < CONV_QUADS) {
        float4 v = (i < OP_QUADS)
                 ? reinterpret_cast<const float4*>(op_feats)[i]
                 : reinterpret_cast<const float4*>(dev_feats)[i - OP_QUADS];
        __half2 h0 = __floats2half2_rn(v.x, v.y);
        __half2 h1 = __floats2half2_rn(v.z, v.w);
        uint2 u;
        u.x = *reinterpret_cast<unsigned*>(&h0);
        u.y = *reinterpret_cast<unsigned*>(&h1);
        reinterpret_cast<uint2*>(g_feats16)[i] = u;
    }
}

// ---------------------------------------------------------------------------
// 1) histogram over all edges (stacked)
// ---------------------------------------------------------------------------
__global__ void hist_kernel(const int* __restrict__ d0, int n0,
                            const int* __restrict__ d1, int n1,
                            const int* __restrict__ d2, int n2,
                            const int* __restrict__ d3, int n3,
                            const int* __restrict__ d4, int n4) {
    int i = blockIdx.x * blockDim.x + threadIdx.x;
    if (i < n0) { atomicAdd(&g_cnt[SEG_PREV  + d0[i]], 1); return; } i -= n0;
    if (i < n1) { atomicAdd(&g_cnt[SEG_SUCC  + d1[i]], 1); return; } i -= n1;
    if (i < n2) { atomicAdd(&g_cnt[SEG_SERVE + d2[i]], 1); return; } i -= n2;
    if (i < n3) { atomicAdd(&g_cnt[SEG_LINK  + d3[i]], 1); return; } i -= n3;
    if (i < n4) { atomicAdd(&g_cnt[SEG_PLACE + d4[i]], 1); }
}

// ---------------------------------------------------------------------------
// 2) per-tile exclusive scan (1024/tile) + tile totals
// ---------------------------------------------------------------------------
__global__ __launch_bounds__(1024)
void scan_tiles_kernel(const int* __restrict__ cnt, int* __restrict__ off,
                       int* __restrict__ tilesum, int n) {
    __shared__ int warp_sums[32];
    int tid  = threadIdx.x;
    int gid  = blockIdx.x * 1024 + tid;
    int lane = tid & 31, wid = tid >> 5;
    int v = (gid < n) ? cnt[gid] : 0;

    int x = v;
    #pragma unroll
    for (int d = 1; d < 32; d <<= 1) {
        int y = __shfl_up_sync(0xffffffffu, x, d);
        if (lane >= d) x += y;
    }
    if (lane == 31) warp_sums[wid] = x;
    __syncthreads();
    if (wid == 0) {
        int s = warp_sums[lane];
        #pragma unroll
        for (int d = 1; d < 32; d <<= 1) {
            int y = __shfl_up_sync(0xffffffffu, s, d);
            if (lane >= d) s += y;
        }
        warp_sums[lane] = s;
    }
    __syncthreads();
    int warp_off = (wid > 0) ? warp_sums[wid - 1] : 0;
    int incl = x + warp_off;
    if (gid < n) off[gid] = incl - v;
    if (tid == 1023) tilesum[blockIdx.x] = incl;
}

// ---------------------------------------------------------------------------
// 3) fixup: add prefix of tile sums, init cursors (one block per tile)
// ---------------------------------------------------------------------------
__global__ __launch_bounds__(1024)
void scan_fixup_kernel(int* __restrict__ off, const int* __restrict__ tilesum,
                       int* __restrict__ cur, int n) {
    __shared__ int red[32];
    __shared__ int s_prefix;
    int t    = blockIdx.x;
    int tid  = threadIdx.x;
    int lane = tid & 31, wid = tid >> 5;

    int partial = 0;
    for (int i = tid; i < t; i += 1024) partial += tilesum[i];
    #pragma unroll
    for (int d = 16; d > 0; d >>= 1)
        partial += __shfl_down_sync(0xffffffffu, partial, d);
    if (lane == 0) red[wid] = partial;
    __syncthreads();
    if (tid < 32) {
        int v = red[tid];
        #pragma unroll
        for (int d = 16; d > 0; d >>= 1)
            v += __shfl_down_sync(0xffffffffu, v, d);
        if (tid == 0) s_prefix = v;
    }
    __syncthreads();
    int prefix = s_prefix;

    int gid = t * 1024 + tid;
    if (gid < n) {
        int o = off[gid] + prefix;
        off[gid] = o;
        cur[gid] = o;
    }
}

// ---------------------------------------------------------------------------
// 4) bin edge IDs into dst buckets
// ---------------------------------------------------------------------------
__global__ void bin_kernel(const int* __restrict__ d0, int n0,
                           const int* __restrict__ d1, int n1,
                           const int* __restrict__ d2, int n2,
                           const int* __restrict__ d3, int n3,
                           const int* __restrict__ d4, int n4) {
    int e = blockIdx.x * blockDim.x + threadIdx.x;
    if (e < n0) { int s = atomicAdd(&g_cur[SEG_PREV  + d0[e]], 1); g_slots[s] = e; return; } e -= n0;
    if (e < n1) { int s = atomicAdd(&g_cur[SEG_SUCC  + d1[e]], 1); g_slots[s] = e; return; } e -= n1;
    if (e < n2) { int s = atomicAdd(&g_cur[SEG_SERVE + d2[e]], 1); g_slots[s] = e; return; } e -= n2;
    if (e < n3) { int s = atomicAdd(&g_cur[SEG_LINK  + d3[e]], 1); g_slots[s] = e; return; } e -= n3;
    if (e < n4) { int s = atomicAdd(&g_cur[SEG_PLACE + d4[e]], 1); g_slots[s] = e; }
}

// ---------------------------------------------------------------------------
// 5) fused gather (fp16 src rows, fp32 accumulation): one warp per segment,
// 4-edge load batching (R8-proven structure). Per edge each lane loads one
// uint2 (4 halves = cols lane*4..lane*4+3) -> 256B per row instead of 512B.
// ---------------------------------------------------------------------------
__global__ __launch_bounds__(256)
void gather_fused_kernel(const float* __restrict__ ef_prev,  const int* __restrict__ src_prev,
                         const float* __restrict__ ef_succ,  const int* __restrict__ src_succ,
                         const float* __restrict__ ef_serve, const int* __restrict__ src_serve,
                         const float* __restrict__ ef_link,  const int* __restrict__ src_link,
                         const float* __restrict__ ef_place, const int* __restrict__ src_place) {
    int seg = blockIdx.x * 8 + (threadIdx.x >> 5);
    if (seg >= NSEG) return;
    const int lane = threadIdx.x & 31;

    const __half* sf; const float* ef; const int* src; float* acc; int local;
    if (seg < SEG_SUCC)       { sf = g_feats16 + F16_OP_BASE;  ef = ef_prev;  src = src_prev;  acc = g_acc + OFF_ACC_PREV;  local = seg; }
    else if (seg < SEG_SERVE) { sf = g_feats16 + F16_OP_BASE;  ef = ef_succ;  src = src_succ;  acc = g_acc + OFF_ACC_SUCC;  local = seg - SEG_SUCC; }
    else if (seg < SEG_LINK)  { sf = g_feats16 + F16_DEV_BASE; ef = ef_serve; src = src_serve; acc = g_acc + OFF_ACC_SERVE; local = seg - SEG_SERVE; }
    else if (seg < SEG_PLACE) { sf = g_feats16 + F16_DEV_BASE; ef = ef_link;  src = src_link;  acc = g_acc + OFF_ACC_LINK;  local = seg - SEG_LINK; }
    else                      { sf = g_feats16 + F16_OP_BASE;  ef = ef_place; src = src_place; acc = g_acc + OFF_ACC_PLACE; local = seg - SEG_PLACE; }

    int m = g_cnt[seg];
    if (m == 0) return;
    int base = g_off[seg];

    float4 f  = make_float4(0.f, 0.f, 0.f, 0.f);
    float4 e4 = make_float4(0.f, 0.f, 0.f, 0.f);  // lanes 0..15: ef chunk (lane&3) partials

    for (int c = 0; c < m; c += 32) {
        int k = c + lane;
        int eidx = 0, sidx = 0;
        if (k < m) {
            eidx = __ldg(&g_slots[base + k]);
            sidx = __ldg(&src[eidx]);
        }
        int iter = min(32, m - c);

        int i = 0;
        for (; i + 4 <= iter; i += 4) {
            int s0 = __shfl_sync(0xffffffffu, sidx, i + 0);
            int s1 = __shfl_sync(0xffffffffu, sidx, i + 1);
            int s2 = __shfl_sync(0xffffffffu, sidx, i + 2);
            int s3 = __shfl_sync(0xffffffffu, sidx, i + 3);
            int emy = __shfl_sync(0xffffffffu, eidx, i + (lane >> 2)); // edge for my ef lane
            // four independent half-row loads (uint2 = 4 halves per lane)
            uint2 u0 = __ldg(reinterpret_cast<const uint2*>(sf + (size_t)s0 * D) + lane);
            uint2 u1 = __ldg(reinterpret_cast<const uint2*>(sf + (size_t)s1 * D) + lane);
            uint2 u2 = __ldg(reinterpret_cast<const uint2*>(sf + (size_t)s2 * D) + lane);
            uint2 u3 = __ldg(reinterpret_cast<const uint2*>(sf + (size_t)s3 * D) + lane);
            if (lane < 16) {
                float4 t = __ldg(reinterpret_cast<const float4*>(ef + (size_t)emy * DE) + (lane & 3));
                e4.x += t.x; e4.y += t.y; e4.z += t.z; e4.w += t.w;
            }
            acc_h4(f, u0);
            acc_h4(f, u1);
            acc_h4(f, u2);
            acc_h4(f, u3);
        }
        // tail (<= 3 edges)
        for (; i < iter; i++) {
            int s = __shfl_sync(0xffffffffu, sidx, i);
            int e = __shfl_sync(0xffffffffu, eidx, i);
            uint2 u = __ldg(reinterpret_cast<const uint2*>(sf + (size_t)s * D) + lane);
            acc_h4(f, u);
            if (lane < 4) {
                float4 t = __ldg(reinterpret_cast<const float4*>(ef + (size_t)e * DE) + lane);
                e4.x += t.x; e4.y += t.y; e4.z += t.z; e4.w += t.w;
            }
        }
    }

    // reduce e4 across the 4 ef-lane groups (lanes {c, c+4, c+8, c+12})
    e4.x += __shfl_xor_sync(0xffffffffu, e4.x, 4);
    e4.y += __shfl_xor_sync(0xffffffffu, e4.y, 4);
    e4.z += __shfl_xor_sync(0xffffffffu, e4.z, 4);
    e4.w += __shfl_xor_sync(0xffffffffu, e4.w, 4);
    e4.x += __shfl_xor_sync(0xffffffffu, e4.x, 8);
    e4.y += __shfl_xor_sync(0xffffffffu, e4.y, 8);
    e4.z += __shfl_xor_sync(0xffffffffu, e4.z, 8);
    e4.w += __shfl_xor_sync(0xffffffffu, e4.w, 8);

    float* arow = acc + (size_t)local * FIN;
    reinterpret_cast<float4*>(arow)[lane] = f;
    if (lane < 4) reinterpret_cast<float4*>(arow + D)[lane] = e4;
}

// ---------------------------------------------------------------------------
// 6) fused GEMM (op + dev tiles in one grid), whole-K smem residency, f32x2.
//    (unchanged from the 508us kernel; identity copy uses original fp32 feats)
// ---------------------------------------------------------------------------
#define AS_STRIDE 145
#define AS_FLOATS (128 * AS_STRIDE)
#define WS_FLOATS (144 * 128)
#define GEMM_SMEM_BYTES ((AS_FLOATS + WS_FLOATS) * 4)

__global__ __launch_bounds__(512)
void gemm_fused_kernel(const float* __restrict__ op_feats,
                       const float* __restrict__ dev_feats,
                       const float* __restrict__ W_prev,  const float* __restrict__ b_prev,
                       const float* __restrict__ W_succ,  const float* __restrict__ b_succ,
                       const float* __restrict__ W_serve, const float* __restrict__ b_serve,
                       const float* __restrict__ W_link,  const float* __restrict__ b_link,
                       const float* __restrict__ W_place, const float* __restrict__ b_place,
                       float* __restrict__ out) {
    extern __shared__ float sm[];
    float* As = sm;                 // [128][145]
    float* Ws = sm + AS_FLOATS;     // [144][128]

    const int tid = threadIdx.x;
    const int r   = tid & 31;
    const int c0  = (tid >> 5) * 8;

    const bool is_op = blockIdx.x < GRID_OP;
    const int  net   = is_op ? 3 : 2;
    const int  row0  = (is_op ? blockIdx.x : (blockIdx.x - GRID_OP)) * 128;
    const int  n     = is_op ? N_OP : N_DEV;

    const float* feats = is_op ? op_feats : dev_feats;
    const float* accA[3]; const int* cntA[3]; const float* WA[3]; const float* bA[3];
    if (is_op) {
        accA[0] = g_acc + OFF_ACC_PREV;  cntA[0] = g_cnt + SEG_PREV;  WA[0] = W_prev;  bA[0] = b_prev;
        accA[1] = g_acc + OFF_ACC_SUCC;  cntA[1] = g_cnt + SEG_SUCC;  WA[1] = W_succ;  bA[1] = b_succ;
        accA[2] = g_acc + OFF_ACC_SERVE; cntA[2] = g_cnt + SEG_SERVE; WA[2] = W_serve; bA[2] = b_serve;
    } else {
        accA[0] = g_acc + OFF_ACC_LINK;  cntA[0] = g_cnt + SEG_LINK;  WA[0] = W_link;  bA[0] = b_link;
        accA[1] = g_acc + OFF_ACC_PLACE; cntA[1] = g_cnt + SEG_PLACE; WA[1] = W_place; bA[1] = b_place;
        accA[2] = accA[1]; cntA[2] = cntA[1]; WA[2] = WA[1]; bA[2] = bA[1];
    }
    float* outp = is_op ? out : (out + (size_t)N_OP * OUT_STRIDE);

    float outv[4][8];
    #pragma unroll
    for (int q = 0; q < 4; q++)
        #pragma unroll
        for (int j = 0; j < 8; j++) outv[q][j] = 0.f;

    for (int et = 0; et < net; et++) {
        const float* acc = accA[et];
        const float* W   = WA[et];

        __syncthreads();
        {
            const float4* W4 = reinterpret_cast<const float4*>(W);
            float4* Ws4 = reinterpret_cast<float4*>(Ws);
            #pragma unroll
            for (int i = 0; i < 9; i++) Ws4[tid + i * 512] = W4[tid + i * 512];
        }
        {
            #pragma unroll
            for (int i = 0; i < 9; i++) {
                int idx = tid + i * 512;
                int rr  = idx / 36;
                int cc  = idx - rr * 36;
                float4 v = make_float4(0.f, 0.f, 0.f, 0.f);
                if (row0 + rr < n)
                    v = reinterpret_cast<const float4*>(acc + (size_t)(row0 + rr) * FIN)[cc];
                float* dst = As + rr * AS_STRIDE + cc * 4;
                dst[0] = v.x; dst[1] = v.y; dst[2] = v.z; dst[3] = v.w;
            }
        }
        __syncthreads();

        unsigned long long p2[4][4];
        #pragma unroll
        for (int q = 0; q < 4; q++)
            #pragma unroll
            for (int j = 0; j < 4; j++) p2[q][j] = 0ull;

        #pragma unroll 4
        for (int k = 0; k < FIN; k++) {
            const unsigned long long* Wrow =
                reinterpret_cast<const unsigned long long*>(Ws + k * 128 + c0);
            unsigned long long w0 = Wrow[0], w1 = Wrow[1], w2 = Wrow[2], w3 = Wrow[3];
            #pragma unroll
            for (int q = 0; q < 4; q++) {
                unsigned long long a2 = pack_dup(As[(r + 32 * q) * AS_STRIDE + k]);
                ffma2(p2[q][0], a2, w0);
                ffma2(p2[q][1], a2, w1);
                ffma2(p2[q][2], a2, w2);
                ffma2(p2[q][3], a2, w3);
            }
        }

        const int*   cnt = cntA[et];
        const float* b   = bA[et];
        #pragma unroll
        for (int q = 0; q < 4; q++) {
            int row = row0 + r + q * 32;
            if (row < n) {
                int c = cnt[row];
                if (c > 0) {
                    float inv = 1.0f / (float)c;
                    #pragma unroll
                    for (int j = 0; j < 4; j++) {
                        float2 pv = unpack2(p2[q][j]);
                        outv[q][2 * j]     += pv.x * inv + b[c0 + 2 * j];
                        outv[q][2 * j + 1] += pv.y * inv + b[c0 + 2 * j + 1];
                    }
                }
            }
        }
    }

    const float invn = is_op ? (1.0f / 3.0f) : 0.5f;
    #pragma unroll
    for (int q = 0; q < 4; q++) {
        int row = row0 + r + q * 32;
        if (row < n) {
            float*       orow = outp  + (size_t)row * OUT_STRIDE;
            const float* frow = feats + (size_t)row * D;
            #pragma unroll
            for (int j = 0; j < 8; j++) {
                orow[c0 + j]     = frow[c0 + j];
                orow[D + c0 + j] = fmaxf(outv[q][j] * invn, 0.f);
            }
        }
    }
}

// ---------------------------------------------------------------------------
// Launch
// ---------------------------------------------------------------------------
extern "C" void kernel_launch(void* const* d_in, const int* in_sizes, int n_in,
                              void* d_out, int out_size) {
    const float* op_feats  = (const float*)d_in[0];
    const float* dev_feats = (const float*)d_in[1];

    const float* ef_link  = (const float*)d_in[2];
    const int*   src_link = (const int*)  d_in[3];
    const int*   dst_link = (const int*)  d_in[4];
    const float* W_link   = (const float*)d_in[5];
    const float* b_link   = (const float*)d_in[6];

    const float* ef_prev  = (const float*)d_in[7];
    const int*   src_prev = (const int*)  d_in[8];
    const int*   dst_prev = (const int*)  d_in[9];
    const float* W_prev   = (const float*)d_in[10];
    const float* b_prev   = (const float*)d_in[11];

    const float* ef_succ  = (const float*)d_in[12];
    const int*   src_succ = (const int*)  d_in[13];
    const int*   dst_succ = (const int*)  d_in[14];
    const float* W_succ   = (const float*)d_in[15];
    const float* b_succ   = (const float*)d_in[16];

    const float* ef_place  = (const float*)d_in[17];
    const int*   src_place = (const int*)  d_in[18];
    const int*   dst_place = (const int*)  d_in[19];
    const float* W_place   = (const float*)d_in[20];
    const float* b_place   = (const float*)d_in[21];

    const float* ef_serve  = (const float*)d_in[22];
    const int*   src_serve = (const int*)  d_in[23];
    const int*   dst_serve = (const int*)  d_in[24];
    const float* W_serve   = (const float*)d_in[25];
    const float* b_serve   = (const float*)d_in[26];

    const int ne_link  = in_sizes[3];
    const int ne_prev  = in_sizes[8];
    const int ne_succ  = in_sizes[13];
    const int ne_place = in_sizes[18];
    const int ne_serve = in_sizes[23];
    const int ne_total = ne_link + ne_prev + ne_succ + ne_place + ne_serve;

    int* cntbase = nullptr;  cudaGetSymbolAddress((void**)&cntbase, g_cnt);
    int* offbase = nullptr;  cudaGetSymbolAddress((void**)&offbase, g_off);
    int* curbase = nullptr;  cudaGetSymbolAddress((void**)&curbase, g_cur);
    int* tilesum = nullptr;  cudaGetSymbolAddress((void**)&tilesum, g_tilesum);

    cudaFuncSetAttribute(gemm_fused_kernel,
                         cudaFuncAttributeMaxDynamicSharedMemorySize,
                         GEMM_SMEM_BYTES);

    // 0) prep: zero counters + fp16 conversion
    prep_kernel<<<(CONV_QUADS + 255) / 256, 256>>>(op_feats, dev_feats);

    // 1) histogram
    hist_kernel<<<(ne_total + 255) / 256, 256>>>(
        dst_prev, ne_prev, dst_succ, ne_succ, dst_serve, ne_serve,
        dst_link, ne_link, dst_place, ne_place);

    // 2-3) scan
    int ntiles = (NSEG + 1023) / 1024;  // 157
    scan_tiles_kernel<<<ntiles, 1024>>>(cntbase, offbase, tilesum, NSEG);
    scan_fixup_kernel<<<ntiles, 1024>>>(offbase, tilesum, curbase, NSEG);

    // 4) bin
    bin_kernel<<<(ne_total + 255) / 256, 256>>>(
        dst_prev, ne_prev, dst_succ, ne_succ, dst_serve, ne_serve,
        dst_link, ne_link, dst_place, ne_place);

    // 5) fused gather (fp16 rows, 4-edge load batching)
    gather_fused_kernel<<<(NSEG + 7) / 8, 256>>>(
        ef_prev, src_prev, ef_succ, src_succ, ef_serve, src_serve,
        ef_link, src_link, ef_place, src_place);

    // 6) fused GEMM
    gemm_fused_kernel<<<GRID_OP + GRID_DEV, 512, GEMM_SMEM_BYTES>>>(
        op_feats, dev_feats,
        W_prev, b_prev, W_succ, b_succ, W_serve, b_serve,
        W_link, b_link, W_place, b_place,
        (float*)d_out);

    (void)n_in; (void)out_size;
}